// round 13
// baseline (speedup 1.0000x reference)
#include <cuda_runtime.h>
#include <cstdint>

#define S_LEN 2048
#define NH    16
#define HD    64
#define NTHR  256
#define BT    128
#define SCALE 0.1875f   // 1.5 / sqrt(64)

#define KS 68
#define VS 72
#define AS 68
// Ks[64*68] | Vs[64*72] | At[128*68]  = 70.7 KB => 2 CTAs/SM (16 warps)
#define SMEM_FLOATS (64*KS + 64*VS + 128*AS)

__device__ __forceinline__ uint32_t f2tf(float x) {
    uint32_t r; asm("cvt.rna.tf32.f32 %0, %1;" : "=r"(r) : "f"(x)); return r;
}

__device__ __forceinline__ void cp16(uint32_t saddr, const float* g) {
    asm volatile("cp.async.cg.shared.global [%0], [%1], 16;" :: "r"(saddr), "l"(g) : "memory");
}

__device__ __forceinline__ void ldsm_x4(uint32_t& r0, uint32_t& r1, uint32_t& r2, uint32_t& r3,
                                        uint32_t saddr) {
    asm volatile("ldmatrix.sync.aligned.m8n8.x4.shared.b16 {%0,%1,%2,%3}, [%4];"
                 : "=r"(r0), "=r"(r1), "=r"(r2), "=r"(r3) : "r"(saddr));
}

__device__ __forceinline__ void mma_tf32(float& d0, float& d1, float& d2, float& d3,
                                         uint32_t a0, uint32_t a1, uint32_t a2, uint32_t a3,
                                         uint32_t b0, uint32_t b1) {
    asm volatile("mma.sync.aligned.m16n8k8.row.col.f32.tf32.tf32.f32 "
                 "{%0,%1,%2,%3}, {%4,%5,%6,%7}, {%8,%9}, {%0,%1,%2,%3};"
                 : "+f"(d0), "+f"(d1), "+f"(d2), "+f"(d3)
                 : "r"(a0), "r"(a1), "r"(a2), "r"(a3), "r"(b0), "r"(b1));
}

// stable sigmoid pair: sg = sigma(x), om = 1 - sigma(x); masked -> sg=0, om=1
__device__ __forceinline__ void sig_pair(float x, bool mask, float& sg, float& om) {
    const float t = __expf(-fabsf(x));          // MUFU exp
    const float r = __fdividef(1.f, 1.f + t);   // MUFU rcp
    const float tr = t * r;
    const bool pos = x >= 0.f;
    sg = mask ? (pos ? r : tr) : 0.f;
    om = mask ? (pos ? tr : r) : 1.f;
}

struct ScanCtx {
    int s0, tg_lo, tg_hi, m0, gp, qd;
    float* At;
};

// scan one j-block (8 keys) of a warp's 16 rows; updates running products
__device__ __forceinline__ void scan_j(const float dj[4], int j, const ScanCtx& c,
                                       float& R_lo, float& R_hi)
{
    const int sg0 = c.s0 + j * 8 + 2 * c.qd;
    const bool m00 = sg0     < c.tg_lo, m01 = sg0 + 1 < c.tg_lo;
    const bool m10 = sg0     < c.tg_hi, m11 = sg0 + 1 < c.tg_hi;

    float sg00, om00, sg01, om01, sg10, om10, sg11, om11;
    sig_pair(dj[0], m00, sg00, om00);
    sig_pair(dj[1], m01, sg01, om01);
    sig_pair(dj[2], m10, sg10, om10);
    sig_pair(dj[3], m11, sg11, om11);

    const float bs_lo = om00 * om01;
    const float bs_hi = om10 * om11;

    // width-4 suffix-inclusive PRODUCT scan over the quad
    float i_lo = bs_lo, i_hi = bs_hi, u;
    u = __shfl_down_sync(0xffffffffu, i_lo, 1, 4); if (c.qd < 3) i_lo *= u;
    u = __shfl_down_sync(0xffffffffu, i_hi, 1, 4); if (c.qd < 3) i_hi *= u;
    u = __shfl_down_sync(0xffffffffu, i_lo, 2, 4); if (c.qd < 2) i_lo *= u;
    u = __shfl_down_sync(0xffffffffu, i_hi, 2, 4); if (c.qd < 2) i_hi *= u;

    float ex_lo = __shfl_down_sync(0xffffffffu, i_lo, 1, 4);
    float ex_hi = __shfl_down_sync(0xffffffffu, i_hi, 1, 4);
    if (c.qd == 3) { ex_lo = 1.f; ex_hi = 1.f; }
    const float T_lo = __shfl_sync(0xffffffffu, i_lo, 0, 4);
    const float T_hi = __shfl_sync(0xffffffffu, i_hi, 0, 4);

    const float E_lo = ex_lo * R_lo;
    const float E_hi = ex_hi * R_hi;

    // att staged with RNA tf32 rounding
    *(float2*)&c.At[(c.m0 + c.gp)     * AS + j * 8 + 2 * c.qd] =
        make_float2(__uint_as_float(f2tf(sg00 * om01 * E_lo)),
                    __uint_as_float(f2tf(sg01 * E_lo)));
    *(float2*)&c.At[(c.m0 + c.gp + 8) * AS + j * 8 + 2 * c.qd] =
        make_float2(__uint_as_float(f2tf(sg10 * om11 * E_hi)),
                    __uint_as_float(f2tf(sg11 * E_hi)));

    R_lo *= T_lo;
    R_hi *= T_hi;
}

// QK for j-pair p (j = 2p, 2p+1): 8 ldsm.x4 + 16 mma
__device__ __forceinline__ void qk_pair(float dlo[4], float dhi[4], uint32_t k_lm, int p,
                                        const uint32_t qa[8][4])
{
    #pragma unroll
    for (int c = 0; c < 4; c++) { dlo[c] = 0.f; dhi[c] = 0.f; }
    #pragma unroll
    for (int ks = 0; ks < 8; ks++) {
        uint32_t b0a, b1a, b0b, b1b;
        ldsm_x4(b0a, b1a, b0b, b1b, k_lm + 4u * (uint32_t)(p * 16 * KS + 8 * ks));
        mma_tf32(dlo[0], dlo[1], dlo[2], dlo[3],
                 qa[ks][0], qa[ks][1], qa[ks][2], qa[ks][3], b0a, b1a);
        mma_tf32(dhi[0], dhi[1], dhi[2], dhi[3],
                 qa[ks][0], qa[ks][1], qa[ks][2], qa[ks][3], b0b, b1b);
    }
}

__global__ void __launch_bounds__(NTHR, 2)
sb_attn_kernel(const float* __restrict__ qkv, float* __restrict__ out)
{
    extern __shared__ float smem[];
    float* Ks = smem;                 // [64][68] raw f32 (tf32 via truncation)
    float* Vs = Ks + 64 * KS;         // [64][72] raw f32
    float* At = Vs + 64 * VS;         // [128][68] att (RNA tf32 bits), per-warp private rows

    const int tt   = (int)gridDim.x - 1 - (int)blockIdx.x;  // heavy tiles first
    const int h    = blockIdx.y;
    const int b    = blockIdx.z;
    const int tid  = threadIdx.x;
    const int warp = tid >> 5;        // 0..7
    const int lane = tid & 31;
    const int gp   = lane >> 2;       // 0..7
    const int qd   = lane & 3;        // 0..3
    const int m0   = warp * 16;       // warp owns rows m0..m0+15 of the 128-row tile
    const int t0   = tt * BT;

    const int tg_lo = t0 + m0 + gp;
    const int tg_hi = tg_lo + 8;

    const uint32_t s_k  = (uint32_t)__cvta_generic_to_shared(Ks);
    const uint32_t s_v  = (uint32_t)__cvta_generic_to_shared(Vs);
    const uint32_t s_at = (uint32_t)__cvta_generic_to_shared(At);

    // ldmatrix per-thread geometry
    const int mat  = lane >> 3;   // 0..3
    const int mrow = lane & 7;
    const uint32_t k_lm = s_k + 4u * ((uint32_t)(((mat >> 1) * 8 + mrow) * KS) + (uint32_t)((mat & 1) * 4));
    const uint32_t at_lm_base = s_at + 4u * ((uint32_t)((m0 + (mat & 1) * 8 + mrow) * AS) + (uint32_t)((mat >> 1) * 4));

    // per-thread staging coords for 64-row K/V tiles: 1024 float4 chunks / 256 thr = 4 each
    const int r0 = tid >> 4;          // 0..15, rows r0 + 16p
    const int c0 = (tid & 15) * 4;

    // ---- Q fragments in registers: RNA tf32, pre-scaled (loaded once) ----
    uint32_t qa[8][4];
    {
        const float* qlo = qkv + (((size_t)b * S_LEN + tg_lo) * 3 + 0) * (NH * HD) + h * HD;
        const float* qhi = qkv + (((size_t)b * S_LEN + tg_hi) * 3 + 0) * (NH * HD) + h * HD;
        #pragma unroll
        for (int ks = 0; ks < 8; ks++) {
            qa[ks][0] = f2tf(SCALE * qlo[ks * 8 + qd]);
            qa[ks][1] = f2tf(SCALE * qhi[ks * 8 + qd]);
            qa[ks][2] = f2tf(SCALE * qlo[ks * 8 + qd + 4]);
            qa[ks][3] = f2tf(SCALE * qhi[ks * 8 + qd + 4]);
        }
    }

    const int kt_top = 2 * tt + 1;    // highest key tile this 128-row block needs

    // ---- Prologue: async-load top K tile ----
    {
        const float* kg = qkv + (((size_t)b * S_LEN + (kt_top * 64 + r0)) * 3 + 1) * (NH * HD) + h * HD + c0;
        #pragma unroll
        for (int p = 0; p < 4; p++)
            cp16(s_k + (uint32_t)((r0 + 16 * p) * KS + c0) * 4u, kg + (size_t)p * 16 * 3 * NH * HD);
        asm volatile("cp.async.commit_group;" ::: "memory");
    }

    float o[8][4];
    #pragma unroll
    for (int j = 0; j < 8; j++)
        #pragma unroll
        for (int c = 0; c < 4; c++) o[j][c] = 0.f;
    float R_lo = 1.f, R_hi = 1.f;

    // ---- Key tiles from the top diagonal down to 0 (suffix order) ----
    for (int kt = kt_top; kt >= 0; --kt) {
        asm volatile("cp.async.wait_group 0;" ::: "memory");   // K_kt landed
        __syncthreads();   // B1: K_kt visible; AV(prev) done -> Vs free

        const int s0 = kt * 64;

        // issue V_kt -> Vs (covered by QK + scan)
        {
            const float* vg = qkv + (((size_t)b * S_LEN + (s0 + r0)) * 3 + 2) * (NH * HD) + h * HD + c0;
            #pragma unroll
            for (int p = 0; p < 4; p++)
                cp16(s_v + (uint32_t)((r0 + 16 * p) * VS + c0) * 4u, vg + (size_t)p * 16 * 3 * NH * HD);
            asm volatile("cp.async.commit_group;" ::: "memory");
        }

        ScanCtx ctx{s0, tg_lo, tg_hi, m0, gp, qd, At};

        // ---- QK (pair-pipelined with the first scans) ----
        float d[8][4];
        qk_pair(d[6], d[7], k_lm, 3, qa);
        qk_pair(d[4], d[5], k_lm, 2, qa);
        scan_j(d[7], 7, ctx, R_lo, R_hi);
        scan_j(d[6], 6, ctx, R_lo, R_hi);
        qk_pair(d[2], d[3], k_lm, 1, qa);
        scan_j(d[5], 5, ctx, R_lo, R_hi);
        scan_j(d[4], 4, ctx, R_lo, R_hi);
        qk_pair(d[0], d[1], k_lm, 0, qa);

        __syncthreads();   // B2: all warps done reading Ks -> buffer reusable

        // mid-tile K prefetch into the SAME buffer (lands during scan tail + AV + B1)
        if (kt > 0) {
            const int s0n = (kt - 1) * 64;
            const float* kg = qkv + (((size_t)b * S_LEN + (s0n + r0)) * 3 + 1) * (NH * HD) + h * HD + c0;
            #pragma unroll
            for (int p = 0; p < 4; p++)
                cp16(s_k + (uint32_t)((r0 + 16 * p) * KS + c0) * 4u, kg + (size_t)p * 16 * 3 * NH * HD);
            asm volatile("cp.async.commit_group;" ::: "memory");
        }

        scan_j(d[3], 3, ctx, R_lo, R_hi);
        scan_j(d[2], 2, ctx, R_lo, R_hi);
        scan_j(d[1], 1, ctx, R_lo, R_hi);
        scan_j(d[0], 0, ctx, R_lo, R_hi);

        // V must have landed (K prefetch may remain in flight)
        if (kt > 0) { asm volatile("cp.async.wait_group 1;" ::: "memory"); }
        else        { asm volatile("cp.async.wait_group 0;" ::: "memory"); }
        __syncthreads();   // B3: V visible; At stores ordered for cross-lane ldmatrix

        // ---- A.V: A-frags via ldmatrix.x4 (one per ks); V scalar ----
        #pragma unroll
        for (int ks = 0; ks < 8; ks++) {
            const int kc = ks * 8;
            uint32_t a0, a1, a2, a3;
            ldsm_x4(a0, a1, a2, a3, at_lm_base + 32u * (uint32_t)ks);
            #pragma unroll
            for (int j = 0; j < 8; j++) {
                uint32_t b0 = __float_as_uint(Vs[(kc + qd)     * VS + j * 8 + gp]);
                uint32_t b1 = __float_as_uint(Vs[(kc + qd + 4) * VS + j * 8 + gp]);
                mma_tf32(o[j][0], o[j][1], o[j][2], o[j][3], a0, a1, a2, a3, b0, b1);
            }
        }
    }

    // ---- Epilogue: out = O + rem * v ; rem is the final running product ----
    const float rem_lo = R_lo;
    const float rem_hi = R_hi;
    #pragma unroll
    for (int j = 0; j < 8; j++) {
        const int n0 = j * 8 + 2 * qd;
        const float* vpa = qkv + (((size_t)b * S_LEN + tg_lo) * 3 + 2) * (NH * HD) + h * HD + n0;
        const float* vpb = qkv + (((size_t)b * S_LEN + tg_hi) * 3 + 2) * (NH * HD) + h * HD + n0;
        float2 va = *(const float2*)vpa;
        float2 vb = *(const float2*)vpb;
        float2 oa = make_float2(o[j][0] + rem_lo * va.x, o[j][1] + rem_lo * va.y);
        float2 ob = make_float2(o[j][2] + rem_hi * vb.x, o[j][3] + rem_hi * vb.y);
        *(float2*)(out + (((size_t)b * S_LEN + tg_lo) * NH + h) * HD + n0) = oa;
        *(float2*)(out + (((size_t)b * S_LEN + tg_hi) * NH + h) * HD + n0) = ob;
    }
}

extern "C" void kernel_launch(void* const* d_in, const int* in_sizes, int n_in,
                              void* d_out, int out_size)
{
    const float* qkv = (const float*)d_in[0];
    float* out = (float*)d_out;

    cudaFuncSetAttribute(sb_attn_kernel,
                         cudaFuncAttributeMaxDynamicSharedMemorySize,
                         SMEM_FLOATS * sizeof(float));

    dim3 grid(S_LEN / BT, NH, 2);   // (16, 16, 2)
    sb_attn_kernel<<<grid, NTHR, SMEM_FLOATS * sizeof(float)>>>(qkv, out);
}

// round 14
// speedup vs baseline: 1.1394x; 1.1394x over previous
#include <cuda_runtime.h>
#include <cstdint>

#define S_LEN 2048
#define NH    16
#define HD    64
#define NTHR  128
#define SCALE 0.1875f   // 1.5 / sqrt(64)

#define KS 68
#define VS 72
#define AS 68
// Ks[64*68] | Vs[64*72] | At[64*68]  — single-buffered, 53.2 KB => 4 CTAs/SM
#define SMEM_FLOATS (64*KS + 64*VS + 64*AS)

__device__ __forceinline__ uint32_t f2tf(float x) {
    uint32_t r; asm("cvt.rna.tf32.f32 %0, %1;" : "=r"(r) : "f"(x)); return r;
}

__device__ __forceinline__ void cp16(uint32_t saddr, const float* g) {
    asm volatile("cp.async.cg.shared.global [%0], [%1], 16;" :: "r"(saddr), "l"(g) : "memory");
}

__device__ __forceinline__ void ldsm_x4(uint32_t& r0, uint32_t& r1, uint32_t& r2, uint32_t& r3,
                                        uint32_t saddr) {
    asm volatile("ldmatrix.sync.aligned.m8n8.x4.shared.b16 {%0,%1,%2,%3}, [%4];"
                 : "=r"(r0), "=r"(r1), "=r"(r2), "=r"(r3) : "r"(saddr));
}

__device__ __forceinline__ void mma_tf32(float& d0, float& d1, float& d2, float& d3,
                                         uint32_t a0, uint32_t a1, uint32_t a2, uint32_t a3,
                                         uint32_t b0, uint32_t b1) {
    asm volatile("mma.sync.aligned.m16n8k8.row.col.f32.tf32.tf32.f32 "
                 "{%0,%1,%2,%3}, {%4,%5,%6,%7}, {%8,%9}, {%0,%1,%2,%3};"
                 : "+f"(d0), "+f"(d1), "+f"(d2), "+f"(d3)
                 : "r"(a0), "r"(a1), "r"(a2), "r"(a3), "r"(b0), "r"(b1));
}

// stable sigmoid pair: sg = sigma(x), om = 1 - sigma(x); masked -> sg=0, om=1
__device__ __forceinline__ void sig_pair(float x, bool mask, float& sg, float& om) {
    const float t = __expf(-fabsf(x));          // MUFU exp
    const float r = __fdividef(1.f, 1.f + t);   // MUFU rcp
    const float tr = t * r;
    const bool pos = x >= 0.f;
    sg = mask ? (pos ? r : tr) : 0.f;
    om = mask ? (pos ? tr : r) : 1.f;
}

struct ScanCtx {
    int s0, tg_lo, tg_hi, m0, gp, qd;
    float* At;
};

// per-j precomputed state: quad totals + pre-attention (att without the R factor)
struct PreJ { float t_lo, t_hi, pa00, pa01, pa10, pa11; };

// phase 1 (parallel across j): sigmoids, quad product scan, pre-att, totals
__device__ __forceinline__ PreJ scan_pre(const float dj[4], int j, const ScanCtx& c)
{
    const int sg0 = c.s0 + j * 8 + 2 * c.qd;
    const bool m00 = sg0     < c.tg_lo, m01 = sg0 + 1 < c.tg_lo;
    const bool m10 = sg0     < c.tg_hi, m11 = sg0 + 1 < c.tg_hi;

    float sg00, om00, sg01, om01, sg10, om10, sg11, om11;
    sig_pair(dj[0], m00, sg00, om00);
    sig_pair(dj[1], m01, sg01, om01);
    sig_pair(dj[2], m10, sg10, om10);
    sig_pair(dj[3], m11, sg11, om11);

    const float bs_lo = om00 * om01;
    const float bs_hi = om10 * om11;

    // width-4 suffix-inclusive PRODUCT scan over the quad
    float i_lo = bs_lo, i_hi = bs_hi, u;
    u = __shfl_down_sync(0xffffffffu, i_lo, 1, 4); if (c.qd < 3) i_lo *= u;
    u = __shfl_down_sync(0xffffffffu, i_hi, 1, 4); if (c.qd < 3) i_hi *= u;
    u = __shfl_down_sync(0xffffffffu, i_lo, 2, 4); if (c.qd < 2) i_lo *= u;
    u = __shfl_down_sync(0xffffffffu, i_hi, 2, 4); if (c.qd < 2) i_hi *= u;

    float ex_lo = __shfl_down_sync(0xffffffffu, i_lo, 1, 4);
    float ex_hi = __shfl_down_sync(0xffffffffu, i_hi, 1, 4);
    if (c.qd == 3) { ex_lo = 1.f; ex_hi = 1.f; }

    PreJ p;
    p.t_lo = __shfl_sync(0xffffffffu, i_lo, 0, 4);
    p.t_hi = __shfl_sync(0xffffffffu, i_hi, 0, 4);
    p.pa00 = sg00 * om01 * ex_lo;
    p.pa01 = sg01 * ex_lo;
    p.pa10 = sg10 * om11 * ex_hi;
    p.pa11 = sg11 * ex_hi;
    return p;
}

// phase 2 (short serial chain): apply R, store att, advance R
__device__ __forceinline__ void scan_fin(const PreJ& p, int j, const ScanCtx& c,
                                         float& R_lo, float& R_hi)
{
    *(float2*)&c.At[(c.m0 + c.gp)     * AS + j * 8 + 2 * c.qd] =
        make_float2(__uint_as_float(f2tf(p.pa00 * R_lo)),
                    __uint_as_float(f2tf(p.pa01 * R_lo)));
    *(float2*)&c.At[(c.m0 + c.gp + 8) * AS + j * 8 + 2 * c.qd] =
        make_float2(__uint_as_float(f2tf(p.pa10 * R_hi)),
                    __uint_as_float(f2tf(p.pa11 * R_hi)));
    R_lo *= p.t_lo;
    R_hi *= p.t_hi;
}

// QK for j-pair p (j = 2p, 2p+1): 8 ldsm.x4 + 16 mma
__device__ __forceinline__ void qk_pair(float dlo[4], float dhi[4], uint32_t k_lm, int p,
                                        const uint32_t qa[8][4])
{
    #pragma unroll
    for (int c = 0; c < 4; c++) { dlo[c] = 0.f; dhi[c] = 0.f; }
    #pragma unroll
    for (int ks = 0; ks < 8; ks++) {
        uint32_t b0a, b1a, b0b, b1b;
        ldsm_x4(b0a, b1a, b0b, b1b, k_lm + 4u * (uint32_t)(p * 16 * KS + 8 * ks));
        mma_tf32(dlo[0], dlo[1], dlo[2], dlo[3],
                 qa[ks][0], qa[ks][1], qa[ks][2], qa[ks][3], b0a, b1a);
        mma_tf32(dhi[0], dhi[1], dhi[2], dhi[3],
                 qa[ks][0], qa[ks][1], qa[ks][2], qa[ks][3], b0b, b1b);
    }
}

__global__ void __launch_bounds__(NTHR, 4)
sb_attn_kernel(const float* __restrict__ qkv, float* __restrict__ out)
{
    extern __shared__ float smem[];
    float* Ks = smem;                 // [64][68] raw f32 (tf32 via truncation)
    float* Vs = Ks + 64 * KS;         // [64][72] raw f32
    float* At = Vs + 64 * VS;         // [64][68] att (RNA tf32 bits), per-warp private rows

    const int tt   = (int)gridDim.x - 1 - (int)blockIdx.x;  // heavy tiles first
    const int h    = blockIdx.y;
    const int b    = blockIdx.z;
    const int tid  = threadIdx.x;
    const int warp = tid >> 5;
    const int lane = tid & 31;
    const int gp   = lane >> 2;   // 0..7
    const int qd   = lane & 3;    // 0..3
    const int m0   = warp * 16;   // warp owns rows m0..m0+15, ALL 64 cols
    const int t0   = tt * 64;

    const int tg_lo = t0 + m0 + gp;
    const int tg_hi = tg_lo + 8;

    const uint32_t s_k  = (uint32_t)__cvta_generic_to_shared(Ks);
    const uint32_t s_v  = (uint32_t)__cvta_generic_to_shared(Vs);
    const uint32_t s_at = (uint32_t)__cvta_generic_to_shared(At);

    // ldmatrix per-thread geometry
    const int mat  = lane >> 3;   // 0..3
    const int mrow = lane & 7;
    const uint32_t k_lm = s_k + 4u * ((uint32_t)(((mat >> 1) * 8 + mrow) * KS) + (uint32_t)((mat & 1) * 4));
    const uint32_t at_lm_base = s_at + 4u * ((uint32_t)((m0 + (mat & 1) * 8 + mrow) * AS) + (uint32_t)((mat >> 1) * 4));

    // per-thread staging coords: c fixed, rows r0 + 8p
    const int r0 = tid >> 4;
    const int c0 = (tid & 15) * 4;

    // ---- Q fragments in registers: RNA tf32, pre-scaled (loaded once) ----
    uint32_t qa[8][4];
    {
        const float* qlo = qkv + (((size_t)b * S_LEN + tg_lo) * 3 + 0) * (NH * HD) + h * HD;
        const float* qhi = qkv + (((size_t)b * S_LEN + tg_hi) * 3 + 0) * (NH * HD) + h * HD;
        #pragma unroll
        for (int ks = 0; ks < 8; ks++) {
            qa[ks][0] = f2tf(SCALE * qlo[ks * 8 + qd]);
            qa[ks][1] = f2tf(SCALE * qhi[ks * 8 + qd]);
            qa[ks][2] = f2tf(SCALE * qlo[ks * 8 + qd + 4]);
            qa[ks][3] = f2tf(SCALE * qhi[ks * 8 + qd + 4]);
        }
    }

    // ---- Prologue: async-load diagonal K tile ----
    {
        const float* kg = qkv + (((size_t)b * S_LEN + (t0 + r0)) * 3 + 1) * (NH * HD) + h * HD + c0;
        #pragma unroll
        for (int p = 0; p < 8; p++)
            cp16(s_k + (uint32_t)((r0 + 8 * p) * KS + c0) * 4u, kg + (size_t)p * 8 * 3 * NH * HD);
        asm volatile("cp.async.commit_group;" ::: "memory");
    }

    float o[8][4];
    #pragma unroll
    for (int j = 0; j < 8; j++)
        #pragma unroll
        for (int c = 0; c < 4; c++) o[j][c] = 0.f;
    float R_lo = 1.f, R_hi = 1.f;

    // ---- Key tiles from diagonal down to 0 (suffix order) ----
    for (int kt = tt; kt >= 0; --kt) {
        asm volatile("cp.async.wait_group 0;" ::: "memory");   // K_kt landed
        __syncthreads();   // B1: K_kt visible; AV(prev) done -> Vs free

        const int s0 = kt * 64;

        // issue V_kt -> Vs (covered by QK + scan)
        {
            const float* vg = qkv + (((size_t)b * S_LEN + (s0 + r0)) * 3 + 2) * (NH * HD) + h * HD + c0;
            #pragma unroll
            for (int p = 0; p < 8; p++)
                cp16(s_v + (uint32_t)((r0 + 8 * p) * VS + c0) * 4u, vg + (size_t)p * 8 * 3 * NH * HD);
            asm volatile("cp.async.commit_group;" ::: "memory");
        }

        ScanCtx ctx{s0, tg_lo, tg_hi, m0, gp, qd, At};

        // ---- QK + two-phase scan ----
        float d[8][4];
        qk_pair(d[6], d[7], k_lm, 3, qa);
        qk_pair(d[4], d[5], k_lm, 2, qa);

        // group A pre (j = 7..4): fully independent streams — fills pipes
        PreJ pA7 = scan_pre(d[7], 7, ctx);
        PreJ pA6 = scan_pre(d[6], 6, ctx);
        PreJ pA5 = scan_pre(d[5], 5, ctx);
        PreJ pA4 = scan_pre(d[4], 4, ctx);

        qk_pair(d[2], d[3], k_lm, 1, qa);
        qk_pair(d[0], d[1], k_lm, 0, qa);

        __syncthreads();   // B2: all warps done reading Ks -> buffer reusable

        // mid-tile K prefetch into the SAME buffer (lands during scan tail + AV + B1)
        if (kt > 0) {
            const int s0n = (kt - 1) * 64;
            const float* kg = qkv + (((size_t)b * S_LEN + (s0n + r0)) * 3 + 1) * (NH * HD) + h * HD + c0;
            #pragma unroll
            for (int p = 0; p < 8; p++)
                cp16(s_k + (uint32_t)((r0 + 8 * p) * KS + c0) * 4u, kg + (size_t)p * 8 * 3 * NH * HD);
            asm volatile("cp.async.commit_group;" ::: "memory");
        }

        // group B pre (j = 3..0): independent streams
        PreJ pB3 = scan_pre(d[3], 3, ctx);
        PreJ pB2 = scan_pre(d[2], 2, ctx);
        PreJ pB1 = scan_pre(d[1], 1, ctx);
        PreJ pB0 = scan_pre(d[0], 0, ctx);

        // serial finish: 1 dependent mul per j (R chain), stores are independent
        scan_fin(pA7, 7, ctx, R_lo, R_hi);
        scan_fin(pA6, 6, ctx, R_lo, R_hi);
        scan_fin(pA5, 5, ctx, R_lo, R_hi);
        scan_fin(pA4, 4, ctx, R_lo, R_hi);
        scan_fin(pB3, 3, ctx, R_lo, R_hi);
        scan_fin(pB2, 2, ctx, R_lo, R_hi);
        scan_fin(pB1, 1, ctx, R_lo, R_hi);
        scan_fin(pB0, 0, ctx, R_lo, R_hi);

        // V must have landed (K prefetch may remain in flight)
        if (kt > 0) { asm volatile("cp.async.wait_group 1;" ::: "memory"); }
        else        { asm volatile("cp.async.wait_group 0;" ::: "memory"); }
        __syncthreads();   // B3: V visible; At stores ordered for cross-lane ldmatrix

        // ---- A.V: A-frags via ldmatrix.x4 (one per ks); V scalar ----
        #pragma unroll
        for (int ks = 0; ks < 8; ks++) {
            const int kc = ks * 8;
            uint32_t a0, a1, a2, a3;
            ldsm_x4(a0, a1, a2, a3, at_lm_base + 32u * (uint32_t)ks);
            #pragma unroll
            for (int j = 0; j < 8; j++) {
                uint32_t b0 = __float_as_uint(Vs[(kc + qd)     * VS + j * 8 + gp]);
                uint32_t b1 = __float_as_uint(Vs[(kc + qd + 4) * VS + j * 8 + gp]);
                mma_tf32(o[j][0], o[j][1], o[j][2], o[j][3], a0, a1, a2, a3, b0, b1);
            }
        }
    }

    // ---- Epilogue: out = O + rem * v ; rem is the final running product ----
    const float rem_lo = R_lo;
    const float rem_hi = R_hi;
    #pragma unroll
    for (int j = 0; j < 8; j++) {
        const int n0 = j * 8 + 2 * qd;
        const float* vpa = qkv + (((size_t)b * S_LEN + tg_lo) * 3 + 2) * (NH * HD) + h * HD + n0;
        const float* vpb = qkv + (((size_t)b * S_LEN + tg_hi) * 3 + 2) * (NH * HD) + h * HD + n0;
        float2 va = *(const float2*)vpa;
        float2 vb = *(const float2*)vpb;
        float2 oa = make_float2(o[j][0] + rem_lo * va.x, o[j][1] + rem_lo * va.y);
        float2 ob = make_float2(o[j][2] + rem_hi * vb.x, o[j][3] + rem_hi * vb.y);
        *(float2*)(out + (((size_t)b * S_LEN + tg_lo) * NH + h) * HD + n0) = oa;
        *(float2*)(out + (((size_t)b * S_LEN + tg_hi) * NH + h) * HD + n0) = ob;
    }
}

extern "C" void kernel_launch(void* const* d_in, const int* in_sizes, int n_in,
                              void* d_out, int out_size)
{
    const float* qkv = (const float*)d_in[0];
    float* out = (float*)d_out;

    cudaFuncSetAttribute(sb_attn_kernel,
                         cudaFuncAttributeMaxDynamicSharedMemorySize,
                         SMEM_FLOATS * sizeof(float));

    dim3 grid(S_LEN / 64, NH, 2);   // (32, 16, 2)
    sb_attn_kernel<<<grid, NTHR, SMEM_FLOATS * sizeof(float)>>>(qkv, out);
}

// round 15
// speedup vs baseline: 1.1927x; 1.0468x over previous
#include <cuda_runtime.h>
#include <cstdint>

#define S_LEN 2048
#define NH    16
#define HD    64
#define NTHR  128
#define SCALE 0.1875f   // 1.5 / sqrt(64)

#define KS 68
#define VS 72
#define AS 68
// Ks[64*68] | Vs[64*72] | At[64*68]  — single-buffered, 53.2 KB => 4 CTAs/SM
#define SMEM_FLOATS (64*KS + 64*VS + 64*AS)

__device__ __forceinline__ uint32_t f2tf(float x) {
    uint32_t r; asm("cvt.rna.tf32.f32 %0, %1;" : "=r"(r) : "f"(x)); return r;
}

__device__ __forceinline__ void cp16(uint32_t saddr, const float* g) {
    asm volatile("cp.async.cg.shared.global [%0], [%1], 16;" :: "r"(saddr), "l"(g) : "memory");
}

__device__ __forceinline__ void ldsm_x4(uint32_t& r0, uint32_t& r1, uint32_t& r2, uint32_t& r3,
                                        uint32_t saddr) {
    asm volatile("ldmatrix.sync.aligned.m8n8.x4.shared.b16 {%0,%1,%2,%3}, [%4];"
                 : "=r"(r0), "=r"(r1), "=r"(r2), "=r"(r3) : "r"(saddr));
}

__device__ __forceinline__ void mma_tf32(float& d0, float& d1, float& d2, float& d3,
                                         uint32_t a0, uint32_t a1, uint32_t a2, uint32_t a3,
                                         uint32_t b0, uint32_t b1) {
    asm volatile("mma.sync.aligned.m16n8k8.row.col.f32.tf32.tf32.f32 "
                 "{%0,%1,%2,%3}, {%4,%5,%6,%7}, {%8,%9}, {%0,%1,%2,%3};"
                 : "+f"(d0), "+f"(d1), "+f"(d2), "+f"(d3)
                 : "r"(a0), "r"(a1), "r"(a2), "r"(a3), "r"(b0), "r"(b1));
}

// stable sigmoid pair: sg = sigma(x), om = 1 - sigma(x)
// MASKED=false: mask statically true — sel/setp layers fold away.
template<bool MASKED>
__device__ __forceinline__ void sig_pair_t(float x, bool mask, float& sg, float& om) {
    const float t = __expf(-fabsf(x));          // MUFU exp
    const float r = __fdividef(1.f, 1.f + t);   // MUFU rcp
    const float tr = t * r;
    const bool pos = x >= 0.f;
    if (MASKED) {
        sg = mask ? (pos ? r : tr) : 0.f;
        om = mask ? (pos ? tr : r) : 1.f;
    } else {
        sg = pos ? r : tr;
        om = pos ? tr : r;
    }
}

struct ScanCtx {
    int s0, tg_lo, tg_hi, m0, gp, qd;
    float* At;
};

// scan one j-block (8 keys) of a warp's 16 rows; updates running products
template<bool MASKED>
__device__ __forceinline__ void scan_j(const float dj[4], int j, const ScanCtx& c,
                                       float& R_lo, float& R_hi)
{
    bool m00 = true, m01 = true, m10 = true, m11 = true;
    if (MASKED) {
        const int sg0 = c.s0 + j * 8 + 2 * c.qd;
        m00 = sg0     < c.tg_lo; m01 = sg0 + 1 < c.tg_lo;
        m10 = sg0     < c.tg_hi; m11 = sg0 + 1 < c.tg_hi;
    }

    float sg00, om00, sg01, om01, sg10, om10, sg11, om11;
    sig_pair_t<MASKED>(dj[0], m00, sg00, om00);
    sig_pair_t<MASKED>(dj[1], m01, sg01, om01);
    sig_pair_t<MASKED>(dj[2], m10, sg10, om10);
    sig_pair_t<MASKED>(dj[3], m11, sg11, om11);

    const float bs_lo = om00 * om01;
    const float bs_hi = om10 * om11;

    // width-4 suffix-inclusive PRODUCT scan over the quad
    float i_lo = bs_lo, i_hi = bs_hi, u;
    u = __shfl_down_sync(0xffffffffu, i_lo, 1, 4); if (c.qd < 3) i_lo *= u;
    u = __shfl_down_sync(0xffffffffu, i_hi, 1, 4); if (c.qd < 3) i_hi *= u;
    u = __shfl_down_sync(0xffffffffu, i_lo, 2, 4); if (c.qd < 2) i_lo *= u;
    u = __shfl_down_sync(0xffffffffu, i_hi, 2, 4); if (c.qd < 2) i_hi *= u;

    float ex_lo = __shfl_down_sync(0xffffffffu, i_lo, 1, 4);
    float ex_hi = __shfl_down_sync(0xffffffffu, i_hi, 1, 4);
    if (c.qd == 3) { ex_lo = 1.f; ex_hi = 1.f; }
    const float T_lo = __shfl_sync(0xffffffffu, i_lo, 0, 4);
    const float T_hi = __shfl_sync(0xffffffffu, i_hi, 0, 4);

    const float E_lo = ex_lo * R_lo;
    const float E_hi = ex_hi * R_hi;

    // att staged with RNA tf32 rounding
    *(float2*)&c.At[(c.m0 + c.gp)     * AS + j * 8 + 2 * c.qd] =
        make_float2(__uint_as_float(f2tf(sg00 * om01 * E_lo)),
                    __uint_as_float(f2tf(sg01 * E_lo)));
    *(float2*)&c.At[(c.m0 + c.gp + 8) * AS + j * 8 + 2 * c.qd] =
        make_float2(__uint_as_float(f2tf(sg10 * om11 * E_hi)),
                    __uint_as_float(f2tf(sg11 * E_hi)));

    R_lo *= T_lo;
    R_hi *= T_hi;
}

// QK for j-pair p (j = 2p, 2p+1): 8 ldsm.x4 + 16 mma
__device__ __forceinline__ void qk_pair(float dlo[4], float dhi[4], uint32_t k_lm, int p,
                                        const uint32_t qa[8][4])
{
    #pragma unroll
    for (int c = 0; c < 4; c++) { dlo[c] = 0.f; dhi[c] = 0.f; }
    #pragma unroll
    for (int ks = 0; ks < 8; ks++) {
        uint32_t b0a, b1a, b0b, b1b;
        ldsm_x4(b0a, b1a, b0b, b1b, k_lm + 4u * (uint32_t)(p * 16 * KS + 8 * ks));
        mma_tf32(dlo[0], dlo[1], dlo[2], dlo[3],
                 qa[ks][0], qa[ks][1], qa[ks][2], qa[ks][3], b0a, b1a);
        mma_tf32(dhi[0], dhi[1], dhi[2], dhi[3],
                 qa[ks][0], qa[ks][1], qa[ks][2], qa[ks][3], b0b, b1b);
    }
}

// full tile body (QK + scan + K-prefetch + AV), specialized on MASKED
template<bool MASKED>
__device__ __forceinline__ void tile_compute(
    int kt, const ScanCtx& ctx, const uint32_t qa[8][4],
    uint32_t k_lm, uint32_t at_lm_base, const float* Vs,
    uint32_t s_k, const float* __restrict__ qkv, int b, int h, int r0, int c0,
    float o[8][4], float& R_lo, float& R_hi)
{
    // ---- QK (pair-pipelined with the first scans) ----
    float d[8][4];
    qk_pair(d[6], d[7], k_lm, 3, qa);
    qk_pair(d[4], d[5], k_lm, 2, qa);
    scan_j<MASKED>(d[7], 7, ctx, R_lo, R_hi);
    scan_j<MASKED>(d[6], 6, ctx, R_lo, R_hi);
    qk_pair(d[2], d[3], k_lm, 1, qa);
    scan_j<MASKED>(d[5], 5, ctx, R_lo, R_hi);
    scan_j<MASKED>(d[4], 4, ctx, R_lo, R_hi);
    qk_pair(d[0], d[1], k_lm, 0, qa);

    __syncthreads();   // B2: all warps done reading Ks -> buffer reusable

    // mid-tile K prefetch into the SAME buffer (lands during scan tail + AV + B1)
    if (kt > 0) {
        const int s0n = (kt - 1) * 64;
        const float* kg = qkv + (((size_t)b * S_LEN + (s0n + r0)) * 3 + 1) * (NH * HD) + h * HD + c0;
        #pragma unroll
        for (int p = 0; p < 8; p++)
            cp16(s_k + (uint32_t)((r0 + 8 * p) * KS + c0) * 4u, kg + (size_t)p * 8 * 3 * NH * HD);
        asm volatile("cp.async.commit_group;" ::: "memory");
    }

    scan_j<MASKED>(d[3], 3, ctx, R_lo, R_hi);
    scan_j<MASKED>(d[2], 2, ctx, R_lo, R_hi);
    scan_j<MASKED>(d[1], 1, ctx, R_lo, R_hi);
    scan_j<MASKED>(d[0], 0, ctx, R_lo, R_hi);

    // V must have landed (K prefetch may remain in flight)
    if (kt > 0) { asm volatile("cp.async.wait_group 1;" ::: "memory"); }
    else        { asm volatile("cp.async.wait_group 0;" ::: "memory"); }
    __syncthreads();   // B3: V visible; At stores ordered for cross-lane ldmatrix

    // ---- A.V: A-frags via ldmatrix.x4 (one per ks); V scalar ----
    const int gp = ctx.gp, qd = ctx.qd;
    #pragma unroll
    for (int ks = 0; ks < 8; ks++) {
        const int kc = ks * 8;
        uint32_t a0, a1, a2, a3;
        ldsm_x4(a0, a1, a2, a3, at_lm_base + 32u * (uint32_t)ks);
        #pragma unroll
        for (int j = 0; j < 8; j++) {
            uint32_t b0 = __float_as_uint(Vs[(kc + qd)     * VS + j * 8 + gp]);
            uint32_t b1 = __float_as_uint(Vs[(kc + qd + 4) * VS + j * 8 + gp]);
            mma_tf32(o[j][0], o[j][1], o[j][2], o[j][3], a0, a1, a2, a3, b0, b1);
        }
    }
}

__global__ void __launch_bounds__(NTHR, 4)
sb_attn_kernel(const float* __restrict__ qkv, float* __restrict__ out)
{
    extern __shared__ float smem[];
    float* Ks = smem;                 // [64][68] raw f32 (tf32 via truncation)
    float* Vs = Ks + 64 * KS;         // [64][72] raw f32
    float* At = Vs + 64 * VS;         // [64][68] att (RNA tf32 bits), per-warp private rows

    const int tt   = (int)gridDim.x - 1 - (int)blockIdx.x;  // heavy tiles first
    const int h    = blockIdx.y;
    const int b    = blockIdx.z;
    const int tid  = threadIdx.x;
    const int warp = tid >> 5;
    const int lane = tid & 31;
    const int gp   = lane >> 2;   // 0..7
    const int qd   = lane & 3;    // 0..3
    const int m0   = warp * 16;   // warp owns rows m0..m0+15, ALL 64 cols
    const int t0   = tt * 64;

    const int tg_lo = t0 + m0 + gp;
    const int tg_hi = tg_lo + 8;

    const uint32_t s_k  = (uint32_t)__cvta_generic_to_shared(Ks);
    const uint32_t s_v  = (uint32_t)__cvta_generic_to_shared(Vs);
    const uint32_t s_at = (uint32_t)__cvta_generic_to_shared(At);

    // ldmatrix per-thread geometry
    const int mat  = lane >> 3;   // 0..3
    const int mrow = lane & 7;
    const uint32_t k_lm = s_k + 4u * ((uint32_t)(((mat >> 1) * 8 + mrow) * KS) + (uint32_t)((mat & 1) * 4));
    const uint32_t at_lm_base = s_at + 4u * ((uint32_t)((m0 + (mat & 1) * 8 + mrow) * AS) + (uint32_t)((mat >> 1) * 4));

    // per-thread staging coords: c fixed, rows r0 + 8p
    const int r0 = tid >> 4;
    const int c0 = (tid & 15) * 4;

    // ---- Q fragments in registers: RNA tf32, pre-scaled (loaded once) ----
    uint32_t qa[8][4];
    {
        const float* qlo = qkv + (((size_t)b * S_LEN + tg_lo) * 3 + 0) * (NH * HD) + h * HD;
        const float* qhi = qkv + (((size_t)b * S_LEN + tg_hi) * 3 + 0) * (NH * HD) + h * HD;
        #pragma unroll
        for (int ks = 0; ks < 8; ks++) {
            qa[ks][0] = f2tf(SCALE * qlo[ks * 8 + qd]);
            qa[ks][1] = f2tf(SCALE * qhi[ks * 8 + qd]);
            qa[ks][2] = f2tf(SCALE * qlo[ks * 8 + qd + 4]);
            qa[ks][3] = f2tf(SCALE * qhi[ks * 8 + qd + 4]);
        }
    }

    // ---- Prologue: async-load diagonal K tile ----
    {
        const float* kg = qkv + (((size_t)b * S_LEN + (t0 + r0)) * 3 + 1) * (NH * HD) + h * HD + c0;
        #pragma unroll
        for (int p = 0; p < 8; p++)
            cp16(s_k + (uint32_t)((r0 + 8 * p) * KS + c0) * 4u, kg + (size_t)p * 8 * 3 * NH * HD);
        asm volatile("cp.async.commit_group;" ::: "memory");
    }

    float o[8][4];
    #pragma unroll
    for (int j = 0; j < 8; j++)
        #pragma unroll
        for (int c = 0; c < 4; c++) o[j][c] = 0.f;
    float R_lo = 1.f, R_hi = 1.f;

    // ---- Key tiles from diagonal down to 0 (suffix order) ----
    for (int kt = tt; kt >= 0; --kt) {
        asm volatile("cp.async.wait_group 0;" ::: "memory");   // K_kt landed
        __syncthreads();   // B1: K_kt visible; AV(prev) done -> Vs free

        const int s0 = kt * 64;

        // issue V_kt -> Vs (covered by QK + scan)
        {
            const float* vg = qkv + (((size_t)b * S_LEN + (s0 + r0)) * 3 + 2) * (NH * HD) + h * HD + c0;
            #pragma unroll
            for (int p = 0; p < 8; p++)
                cp16(s_v + (uint32_t)((r0 + 8 * p) * VS + c0) * 4u, vg + (size_t)p * 8 * 3 * NH * HD);
            asm volatile("cp.async.commit_group;" ::: "memory");
        }

        ScanCtx ctx{s0, tg_lo, tg_hi, m0, gp, qd, At};

        // diagonal tile needs masks; all inner tiles are provably unmasked
        if (kt == tt) {
            tile_compute<true >(kt, ctx, qa, k_lm, at_lm_base, Vs, s_k, qkv, b, h, r0, c0,
                                o, R_lo, R_hi);
        } else {
            tile_compute<false>(kt, ctx, qa, k_lm, at_lm_base, Vs, s_k, qkv, b, h, r0, c0,
                                o, R_lo, R_hi);
        }
    }

    // ---- Epilogue: out = O + rem * v ; rem is the final running product ----
    const float rem_lo = R_lo;
    const float rem_hi = R_hi;
    #pragma unroll
    for (int j = 0; j < 8; j++) {
        const int n0 = j * 8 + 2 * qd;
        const float* vpa = qkv + (((size_t)b * S_LEN + tg_lo) * 3 + 2) * (NH * HD) + h * HD + n0;
        const float* vpb = qkv + (((size_t)b * S_LEN + tg_hi) * 3 + 2) * (NH * HD) + h * HD + n0;
        float2 va = *(const float2*)vpa;
        float2 vb = *(const float2*)vpb;
        float2 oa = make_float2(o[j][0] + rem_lo * va.x, o[j][1] + rem_lo * va.y);
        float2 ob = make_float2(o[j][2] + rem_hi * vb.x, o[j][3] + rem_hi * vb.y);
        *(float2*)(out + (((size_t)b * S_LEN + tg_lo) * NH + h) * HD + n0) = oa;
        *(float2*)(out + (((size_t)b * S_LEN + tg_hi) * NH + h) * HD + n0) = ob;
    }
}

extern "C" void kernel_launch(void* const* d_in, const int* in_sizes, int n_in,
                              void* d_out, int out_size)
{
    const float* qkv = (const float*)d_in[0];
    float* out = (float*)d_out;

    cudaFuncSetAttribute(sb_attn_kernel,
                         cudaFuncAttributeMaxDynamicSharedMemorySize,
                         SMEM_FLOATS * sizeof(float));

    dim3 grid(S_LEN / 64, NH, 2);   // (32, 16, 2)
    sb_attn_kernel<<<grid, NTHR, SMEM_FLOATS * sizeof(float)>>>(qkv, out);
}

// round 16
// speedup vs baseline: 1.4749x; 1.2366x over previous
#include <cuda_runtime.h>
#include <cstdint>

#define S_LEN 2048
#define NH    16
#define HD    64
#define NTHR  128
#define SCALE 0.1875f   // 1.5 / sqrt(64)

#define KS 68
#define VS 72
#define AS 68
// Ks[64*68] | Vs[64*72] | At[64*68]  — single-buffered, 53.2 KB => 4 CTAs/SM
#define SMEM_FLOATS (64*KS + 64*VS + 64*AS)

__device__ __forceinline__ uint32_t f2tf(float x) {
    uint32_t r; asm("cvt.rna.tf32.f32 %0, %1;" : "=r"(r) : "f"(x)); return r;
}

__device__ __forceinline__ void cp16(uint32_t saddr, const float* g) {
    asm volatile("cp.async.cg.shared.global [%0], [%1], 16;" :: "r"(saddr), "l"(g) : "memory");
}

__device__ __forceinline__ void ldsm_x4(uint32_t& r0, uint32_t& r1, uint32_t& r2, uint32_t& r3,
                                        uint32_t saddr) {
    asm volatile("ldmatrix.sync.aligned.m8n8.x4.shared.b16 {%0,%1,%2,%3}, [%4];"
                 : "=r"(r0), "=r"(r1), "=r"(r2), "=r"(r3) : "r"(saddr));
}

__device__ __forceinline__ void mma_tf32(float& d0, float& d1, float& d2, float& d3,
                                         uint32_t a0, uint32_t a1, uint32_t a2, uint32_t a3,
                                         uint32_t b0, uint32_t b1) {
    asm volatile("mma.sync.aligned.m16n8k8.row.col.f32.tf32.tf32.f32 "
                 "{%0,%1,%2,%3}, {%4,%5,%6,%7}, {%8,%9}, {%0,%1,%2,%3};"
                 : "+f"(d0), "+f"(d1), "+f"(d2), "+f"(d3)
                 : "r"(a0), "r"(a1), "r"(a2), "r"(a3), "r"(b0), "r"(b1));
}

// stable sigmoid pair: sg = sigma(x), om = 1 - sigma(x)
// MASKED=false: mask statically true — sel/setp layers fold away.
template<bool MASKED>
__device__ __forceinline__ void sig_pair_t(float x, bool mask, float& sg, float& om) {
    const float t = __expf(-fabsf(x));          // MUFU exp
    const float r = __fdividef(1.f, 1.f + t);   // MUFU rcp
    const float tr = t * r;
    const bool pos = x >= 0.f;
    if (MASKED) {
        sg = mask ? (pos ? r : tr) : 0.f;
        om = mask ? (pos ? tr : r) : 1.f;
    } else {
        sg = pos ? r : tr;
        om = pos ? tr : r;
    }
}

struct ScanCtx {
    int s0, tg_lo, tg_hi, m0, gp, qd;
    float* At;
};

// scan one j-block (8 keys) of a warp's 16 rows; updates running products
template<bool MASKED>
__device__ __forceinline__ void scan_j(const float dj[4], int j, const ScanCtx& c,
                                       float& R_lo, float& R_hi)
{
    bool m00 = true, m01 = true, m10 = true, m11 = true;
    if (MASKED) {
        const int sg0 = c.s0 + j * 8 + 2 * c.qd;
        m00 = sg0     < c.tg_lo; m01 = sg0 + 1 < c.tg_lo;
        m10 = sg0     < c.tg_hi; m11 = sg0 + 1 < c.tg_hi;
    }

    float sg00, om00, sg01, om01, sg10, om10, sg11, om11;
    sig_pair_t<MASKED>(dj[0], m00, sg00, om00);
    sig_pair_t<MASKED>(dj[1], m01, sg01, om01);
    sig_pair_t<MASKED>(dj[2], m10, sg10, om10);
    sig_pair_t<MASKED>(dj[3], m11, sg11, om11);

    const float bs_lo = om00 * om01;
    const float bs_hi = om10 * om11;

    // width-4 suffix-inclusive PRODUCT scan over the quad
    float i_lo = bs_lo, i_hi = bs_hi, u;
    u = __shfl_down_sync(0xffffffffu, i_lo, 1, 4); if (c.qd < 3) i_lo *= u;
    u = __shfl_down_sync(0xffffffffu, i_hi, 1, 4); if (c.qd < 3) i_hi *= u;
    u = __shfl_down_sync(0xffffffffu, i_lo, 2, 4); if (c.qd < 2) i_lo *= u;
    u = __shfl_down_sync(0xffffffffu, i_hi, 2, 4); if (c.qd < 2) i_hi *= u;

    float ex_lo = __shfl_down_sync(0xffffffffu, i_lo, 1, 4);
    float ex_hi = __shfl_down_sync(0xffffffffu, i_hi, 1, 4);
    if (c.qd == 3) { ex_lo = 1.f; ex_hi = 1.f; }
    const float T_lo = __shfl_sync(0xffffffffu, i_lo, 0, 4);
    const float T_hi = __shfl_sync(0xffffffffu, i_hi, 0, 4);

    const float E_lo = ex_lo * R_lo;
    const float E_hi = ex_hi * R_hi;

    // att staged with RNA tf32 rounding
    *(float2*)&c.At[(c.m0 + c.gp)     * AS + j * 8 + 2 * c.qd] =
        make_float2(__uint_as_float(f2tf(sg00 * om01 * E_lo)),
                    __uint_as_float(f2tf(sg01 * E_lo)));
    *(float2*)&c.At[(c.m0 + c.gp + 8) * AS + j * 8 + 2 * c.qd] =
        make_float2(__uint_as_float(f2tf(sg10 * om11 * E_hi)),
                    __uint_as_float(f2tf(sg11 * E_hi)));

    R_lo *= T_lo;
    R_hi *= T_hi;
}

// QK for j-pair p (j = 2p, 2p+1): 8 ldsm.x4 + 16 mma
__device__ __forceinline__ void qk_pair(float dlo[4], float dhi[4], uint32_t k_lm, int p,
                                        const uint32_t qa[8][4])
{
    #pragma unroll
    for (int c = 0; c < 4; c++) { dlo[c] = 0.f; dhi[c] = 0.f; }
    #pragma unroll
    for (int ks = 0; ks < 8; ks++) {
        uint32_t b0a, b1a, b0b, b1b;
        ldsm_x4(b0a, b1a, b0b, b1b, k_lm + 4u * (uint32_t)(p * 16 * KS + 8 * ks));
        mma_tf32(dlo[0], dlo[1], dlo[2], dlo[3],
                 qa[ks][0], qa[ks][1], qa[ks][2], qa[ks][3], b0a, b1a);
        mma_tf32(dhi[0], dhi[1], dhi[2], dhi[3],
                 qa[ks][0], qa[ks][1], qa[ks][2], qa[ks][3], b0b, b1b);
    }
}

// full tile body (QK + scan + K-prefetch + AV), specialized on MASKED
template<bool MASKED>
__device__ __forceinline__ void tile_compute(
    int kt, const ScanCtx& ctx, const uint32_t qa[8][4],
    uint32_t k_lm, uint32_t at_lm_base, const float* Vs,
    uint32_t s_k, const float* __restrict__ qkv, int b, int h, int r0, int c0,
    float o[8][4], float& R_lo, float& R_hi)
{
    // ---- QK (pair-pipelined with the first scans) ----
    float d[8][4];
    qk_pair(d[6], d[7], k_lm, 3, qa);
    qk_pair(d[4], d[5], k_lm, 2, qa);
    scan_j<MASKED>(d[7], 7, ctx, R_lo, R_hi);
    scan_j<MASKED>(d[6], 6, ctx, R_lo, R_hi);
    qk_pair(d[2], d[3], k_lm, 1, qa);
    scan_j<MASKED>(d[5], 5, ctx, R_lo, R_hi);
    scan_j<MASKED>(d[4], 4, ctx, R_lo, R_hi);
    qk_pair(d[0], d[1], k_lm, 0, qa);

    __syncthreads();   // B2: all warps done reading Ks -> buffer reusable

    // mid-tile K prefetch into the SAME buffer (lands during scan tail + AV + B1)
    if (kt > 0) {
        const int s0n = (kt - 1) * 64;
        const float* kg = qkv + (((size_t)b * S_LEN + (s0n + r0)) * 3 + 1) * (NH * HD) + h * HD + c0;
        #pragma unroll
        for (int p = 0; p < 8; p++)
            cp16(s_k + (uint32_t)((r0 + 8 * p) * KS + c0) * 4u, kg + (size_t)p * 8 * 3 * NH * HD);
        asm volatile("cp.async.commit_group;" ::: "memory");
    }

    scan_j<MASKED>(d[3], 3, ctx, R_lo, R_hi);
    scan_j<MASKED>(d[2], 2, ctx, R_lo, R_hi);
    scan_j<MASKED>(d[1], 1, ctx, R_lo, R_hi);
    scan_j<MASKED>(d[0], 0, ctx, R_lo, R_hi);

    // V must have landed (K prefetch may remain in flight)
    if (kt > 0) { asm volatile("cp.async.wait_group 1;" ::: "memory"); }
    else        { asm volatile("cp.async.wait_group 0;" ::: "memory"); }
    __syncthreads();   // B3: V visible; At stores ordered for cross-lane ldmatrix

    // ---- A.V: A-frags via ldmatrix.x4 (one per ks); V scalar ----
    const int gp = ctx.gp, qd = ctx.qd;
    #pragma unroll
    for (int ks = 0; ks < 8; ks++) {
        const int kc = ks * 8;
        uint32_t a0, a1, a2, a3;
        ldsm_x4(a0, a1, a2, a3, at_lm_base + 32u * (uint32_t)ks);
        #pragma unroll
        for (int j = 0; j < 8; j++) {
            uint32_t b0 = __float_as_uint(Vs[(kc + qd)     * VS + j * 8 + gp]);
            uint32_t b1 = __float_as_uint(Vs[(kc + qd + 4) * VS + j * 8 + gp]);
            mma_tf32(o[j][0], o[j][1], o[j][2], o[j][3], a0, a1, a2, a3, b0, b1);
        }
    }
}

__global__ void __launch_bounds__(NTHR, 4)
sb_attn_kernel(const float* __restrict__ qkv, float* __restrict__ out)
{
    extern __shared__ float smem[];
    float* Ks = smem;                 // [64][68] raw f32 (tf32 via truncation)
    float* Vs = Ks + 64 * KS;         // [64][72] raw f32
    float* At = Vs + 64 * VS;         // [64][68] att (RNA tf32 bits), per-warp private rows

    // LPT grid mapping: x = (h,b) combo [fast dim], y = tile rank [slow dim].
    // Launch order emits ALL tt=31 CTAs (32 units of work) first, then tt=30, ...
    // => global longest-processing-time-first schedule, makespan ~= heaviest job.
    const int hb   = (int)blockIdx.x;          // 0..31
    const int h    = hb & 15;
    const int b    = hb >> 4;
    const int tt   = (int)gridDim.y - 1 - (int)blockIdx.y;   // 31..0, heavy first

    const int tid  = threadIdx.x;
    const int warp = tid >> 5;
    const int lane = tid & 31;
    const int gp   = lane >> 2;   // 0..7
    const int qd   = lane & 3;    // 0..3
    const int m0   = warp * 16;   // warp owns rows m0..m0+15, ALL 64 cols
    const int t0   = tt * 64;

    const int tg_lo = t0 + m0 + gp;
    const int tg_hi = tg_lo + 8;

    const uint32_t s_k  = (uint32_t)__cvta_generic_to_shared(Ks);
    const uint32_t s_v  = (uint32_t)__cvta_generic_to_shared(Vs);
    const uint32_t s_at = (uint32_t)__cvta_generic_to_shared(At);

    // ldmatrix per-thread geometry
    const int mat  = lane >> 3;   // 0..3
    const int mrow = lane & 7;
    const uint32_t k_lm = s_k + 4u * ((uint32_t)(((mat >> 1) * 8 + mrow) * KS) + (uint32_t)((mat & 1) * 4));
    const uint32_t at_lm_base = s_at + 4u * ((uint32_t)((m0 + (mat & 1) * 8 + mrow) * AS) + (uint32_t)((mat >> 1) * 4));

    // per-thread staging coords: c fixed, rows r0 + 8p
    const int r0 = tid >> 4;
    const int c0 = (tid & 15) * 4;

    // ---- Q fragments in registers: RNA tf32, pre-scaled (loaded once) ----
    uint32_t qa[8][4];
    {
        const float* qlo = qkv + (((size_t)b * S_LEN + tg_lo) * 3 + 0) * (NH * HD) + h * HD;
        const float* qhi = qkv + (((size_t)b * S_LEN + tg_hi) * 3 + 0) * (NH * HD) + h * HD;
        #pragma unroll
        for (int ks = 0; ks < 8; ks++) {
            qa[ks][0] = f2tf(SCALE * qlo[ks * 8 + qd]);
            qa[ks][1] = f2tf(SCALE * qhi[ks * 8 + qd]);
            qa[ks][2] = f2tf(SCALE * qlo[ks * 8 + qd + 4]);
            qa[ks][3] = f2tf(SCALE * qhi[ks * 8 + qd + 4]);
        }
    }

    // ---- Prologue: async-load diagonal K tile ----
    {
        const float* kg = qkv + (((size_t)b * S_LEN + (t0 + r0)) * 3 + 1) * (NH * HD) + h * HD + c0;
        #pragma unroll
        for (int p = 0; p < 8; p++)
            cp16(s_k + (uint32_t)((r0 + 8 * p) * KS + c0) * 4u, kg + (size_t)p * 8 * 3 * NH * HD);
        asm volatile("cp.async.commit_group;" ::: "memory");
    }

    float o[8][4];
    #pragma unroll
    for (int j = 0; j < 8; j++)
        #pragma unroll
        for (int c = 0; c < 4; c++) o[j][c] = 0.f;
    float R_lo = 1.f, R_hi = 1.f;

    // ---- Key tiles from diagonal down to 0 (suffix order) ----
    for (int kt = tt; kt >= 0; --kt) {
        asm volatile("cp.async.wait_group 0;" ::: "memory");   // K_kt landed
        __syncthreads();   // B1: K_kt visible; AV(prev) done -> Vs free

        const int s0 = kt * 64;

        // issue V_kt -> Vs (covered by QK + scan)
        {
            const float* vg = qkv + (((size_t)b * S_LEN + (s0 + r0)) * 3 + 2) * (NH * HD) + h * HD + c0;
            #pragma unroll
            for (int p = 0; p < 8; p++)
                cp16(s_v + (uint32_t)((r0 + 8 * p) * VS + c0) * 4u, vg + (size_t)p * 8 * 3 * NH * HD);
            asm volatile("cp.async.commit_group;" ::: "memory");
        }

        ScanCtx ctx{s0, tg_lo, tg_hi, m0, gp, qd, At};

        // diagonal tile needs masks; all inner tiles are provably unmasked
        if (kt == tt) {
            tile_compute<true >(kt, ctx, qa, k_lm, at_lm_base, Vs, s_k, qkv, b, h, r0, c0,
                                o, R_lo, R_hi);
        } else {
            tile_compute<false>(kt, ctx, qa, k_lm, at_lm_base, Vs, s_k, qkv, b, h, r0, c0,
                                o, R_lo, R_hi);
        }
    }

    // ---- Epilogue: out = O + rem * v ; rem is the final running product ----
    const float rem_lo = R_lo;
    const float rem_hi = R_hi;
    #pragma unroll
    for (int j = 0; j < 8; j++) {
        const int n0 = j * 8 + 2 * qd;
        const float* vpa = qkv + (((size_t)b * S_LEN + tg_lo) * 3 + 2) * (NH * HD) + h * HD + n0;
        const float* vpb = qkv + (((size_t)b * S_LEN + tg_hi) * 3 + 2) * (NH * HD) + h * HD + n0;
        float2 va = *(const float2*)vpa;
        float2 vb = *(const float2*)vpb;
        float2 oa = make_float2(o[j][0] + rem_lo * va.x, o[j][1] + rem_lo * va.y);
        float2 ob = make_float2(o[j][2] + rem_hi * vb.x, o[j][3] + rem_hi * vb.y);
        *(float2*)(out + (((size_t)b * S_LEN + tg_lo) * NH + h) * HD + n0) = oa;
        *(float2*)(out + (((size_t)b * S_LEN + tg_hi) * NH + h) * HD + n0) = ob;
    }
}

extern "C" void kernel_launch(void* const* d_in, const int* in_sizes, int n_in,
                              void* d_out, int out_size)
{
    const float* qkv = (const float*)d_in[0];
    float* out = (float*)d_out;

    cudaFuncSetAttribute(sb_attn_kernel,
                         cudaFuncAttributeMaxDynamicSharedMemorySize,
                         SMEM_FLOATS * sizeof(float));

    // x = 32 (h,b) combos [fast], y = 32 tile ranks [slow] => global LPT order
    dim3 grid(NH * 2, S_LEN / 64, 1);   // (32, 32, 1)
    sb_attn_kernel<<<grid, NTHR, SMEM_FLOATS * sizeof(float)>>>(qkv, out);
}